// round 13
// baseline (speedup 1.0000x reference)
#include <cuda_runtime.h>
#include <math.h>
#include <stdint.h>

typedef unsigned long long ull;
typedef unsigned int u32;
typedef unsigned short u16;

#define NNODE 307
#define NP    320
#define BATCH 512
#define CIN   5
#define HID   16
#define KORD  6
#define BH    8192          // BATCH*HID
#define BC    2560          // BATCH*CIN
#define NPBC  (NP*BC)

// ------------------------------ scratch ------------------------------------
__device__ __align__(256) float g_En[NNODE * 10];
__device__ __align__(256) float g_dinv[NNODE];
__device__ __align__(256) float g_L[NP * NP];
__device__ __align__(256) u16 g_Lhi[NP * NP];
__device__ __align__(256) u16 g_Llo[NP * NP];
__device__ __align__(256) float g_Y[KORD * NPBC];
__device__ __align__(256) float g_SA[NP * BH];
__device__ __align__(256) float g_SB[NP * BH];
__device__ __align__(256) float g_T[NP * BH];
__device__ __align__(256) float g_U[NP * BH];
// bf16 hi/lo shadows for GL inputs
__device__ __align__(256) u16 g_HAhi[NP * BH];
__device__ __align__(256) u16 g_HAlo[NP * BH];
__device__ __align__(256) u16 g_HBhi[NP * BH];
__device__ __align__(256) u16 g_HBlo[NP * BH];
__device__ __align__(256) u16 g_HUhi[NP * BH];
__device__ __align__(256) u16 g_HUlo[NP * BH];

// ------------------------------ helpers ------------------------------------
__device__ __forceinline__ ull pack2(float x, float y) {
    ull d; asm("mov.b64 %0, {%1, %2};" : "=l"(d) : "f"(x), "f"(y)); return d;
}
__device__ __forceinline__ void unpack2(ull v, float& x, float& y) {
    asm("mov.b64 {%0, %1}, %2;" : "=f"(x), "=f"(y) : "l"(v));
}
__device__ __forceinline__ ull fma2(ull a, ull b, ull c) {
    ull d; asm("fma.rn.f32x2 %0, %1, %2, %3;" : "=l"(d) : "l"(a), "l"(b), "l"(c));
    return d;
}
__device__ __forceinline__ float ftanh(float x) {
    float e; asm("ex2.approx.f32 %0, %1;" : "=f"(e) : "f"(x * 2.885390082f));
    float r; asm("rcp.approx.f32 %0, %1;" : "=f"(r) : "f"(e + 1.0f));
    return fmaf(-2.0f, r, 1.0f);
}
__device__ __forceinline__ float fsig(float x) {
    return fmaf(0.5f, ftanh(0.5f * x), 0.5f);
}
__device__ __forceinline__ u32 smem_u32(const void* p) {
    u32 a;
    asm("{ .reg .u64 t; cvta.to.shared.u64 t, %1; cvt.u32.u64 %0, t; }"
        : "=r"(a) : "l"(p));
    return a;
}
__device__ __forceinline__ void hmma(float* d, const u32* a, u32 b0, u32 b1) {
    asm volatile("mma.sync.aligned.m16n8k16.row.col.f32.bf16.bf16.f32 "
        "{%0,%1,%2,%3}, {%4,%5,%6,%7}, {%8,%9}, {%0,%1,%2,%3};"
        : "+f"(d[0]), "+f"(d[1]), "+f"(d[2]), "+f"(d[3])
        : "r"(a[0]), "r"(a[1]), "r"(a[2]), "r"(a[3]), "r"(b0), "r"(b1));
}
__device__ __forceinline__ void ldsm4(u32* r, u32 addr) {
    asm volatile("ldmatrix.sync.aligned.m8n8.x4.shared.b16 {%0,%1,%2,%3}, [%4];"
        : "=r"(r[0]), "=r"(r[1]), "=r"(r[2]), "=r"(r[3]) : "r"(addr));
}
__device__ __forceinline__ void ldsm4t(u32* r, u32 addr) {
    asm volatile("ldmatrix.sync.aligned.m8n8.x4.trans.shared.b16 {%0,%1,%2,%3}, [%4];"
        : "=r"(r[0]), "=r"(r[1]), "=r"(r[2]), "=r"(r[3]) : "r"(addr));
}
// split two floats into packed bf16 hi (truncate) and lo (rn residual)
__device__ __forceinline__ void split2(float v0, float v1, u32& hi, u32& lo) {
    u32 ba = __float_as_uint(v0), bb = __float_as_uint(v1);
    asm("prmt.b32 %0, %1, %2, 0x7632;" : "=r"(hi) : "r"(ba), "r"(bb));
    float ra = v0 - __uint_as_float(ba & 0xFFFF0000u);
    float rb = v1 - __uint_as_float(bb & 0xFFFF0000u);
    asm("cvt.rn.bf16x2.f32 %0, %1, %2;" : "=r"(lo) : "f"(rb), "f"(ra));
}

// ------------------------------ setup ---------------------------------------
__global__ void __launch_bounds__(320) k_norm(const float* __restrict__ E) {
    __shared__ float sSum[10];
    int t = threadIdx.x;
    if (t < 10) sSum[t] = 0.f;
    __syncthreads();
    float e[10];
    if (t < NNODE) {
        float s = 0.f;
#pragma unroll
        for (int c = 0; c < 10; c++) { e[c] = E[t * 10 + c]; s += e[c] * e[c]; }
        float inv = rsqrtf(s);
#pragma unroll
        for (int c = 0; c < 10; c++) {
            e[c] *= inv;
            g_En[t * 10 + c] = e[c];
            atomicAdd(&sSum[c], e[c]);
        }
    }
    __syncthreads();
    if (t < NNODE) {
        float d = 0.f;
#pragma unroll
        for (int c = 0; c < 10; c++) d += e[c] * sSum[c];
        g_dinv[t] = rsqrtf(d);
    }
}

__global__ void k_lap() {
    int idx = blockIdx.x * 256 + threadIdx.x;
    if (idx >= NP * NP) return;
    int n = idx / NP, m = idx % NP;
    float v = 0.f;
    if (n < NNODE && m < NNODE) {
        float dot = 0.f;
#pragma unroll
        for (int c = 0; c < 10; c++) dot += g_En[n * 10 + c] * g_En[m * 10 + c];
        v = ((n == m) ? 1.f : 0.f) - g_dinv[n] * dot * g_dinv[m];
    }
    g_L[idx] = v;
    u32 bits = __float_as_uint(v);
    float res = v - __uint_as_float(bits & 0xFFFF0000u);
    u16 lo16;
    asm("cvt.rn.bf16.f32 %0, %1;" : "=h"(lo16) : "f"(res));
    g_Lhi[idx] = (u16)(bits >> 16);
    g_Llo[idx] = lo16;
}

__global__ void k_xt(const float* __restrict__ flow, float* __restrict__ Y0) {
    int idx = blockIdx.x * 128 + threadIdx.x;
    if (idx >= NP * BATCH) return;
    int n = idx >> 9, b = idx & 511;
#pragma unroll
    for (int c = 0; c < CIN; c++) {
        float v = 0.f;
        if (n < NNODE) v = flow[((size_t)b * NNODE + n) * CIN + c];
        Y0[(size_t)n * BC + b * CIN + c] = v;
    }
}

// ====== cheb mainloop (R6, proven): 64x64 tile, 4x4/thread, double buffer ===
__device__ __forceinline__ void gemm_mainloop_db(
    const float* __restrict__ Bsrc, int ld, int row0, int col0,
    float* sm, ull acc[4][2])
{
    int tid = threadIdx.x;
    int tx = tid & 15, ty = tid >> 4;
    int a_r = tid >> 2, a_c4 = (tid & 3) << 2;
    int b_r = tid >> 4, b_c4 = (tid & 15) << 2;
    const float* Ap = g_L + (size_t)(row0 + a_r) * NP + a_c4;
    const float* Bp = Bsrc + (size_t)b_r * ld + col0 + b_c4;

    float4 rA = *(const float4*)(Ap);
    float4 rB = *(const float4*)(Bp);
    {
        float* As = sm;
        float* Bs = sm + 1152;
        As[(a_c4 + 0) * 72 + a_r] = rA.x; As[(a_c4 + 1) * 72 + a_r] = rA.y;
        As[(a_c4 + 2) * 72 + a_r] = rA.z; As[(a_c4 + 3) * 72 + a_r] = rA.w;
        *(float4*)(Bs + b_r * 72 + b_c4) = rB;
    }
    __syncthreads();

#pragma unroll 1
    for (int t = 0; t < 20; t++) {
        const float* Ac = sm + (t & 1) * 2304;
        const float* Bc = Ac + 1152;
        if (t < 19) {
            rA = *(const float4*)(Ap + (t + 1) * 16);
            rB = *(const float4*)(Bp + (size_t)((t + 1) * 16) * ld);
        }
#pragma unroll
        for (int kk = 0; kk < 16; kk++) {
            float4 a = *(const float4*)(Ac + kk * 72 + (ty << 2));
            ulonglong2 bb = *(const ulonglong2*)(Bc + kk * 72 + (tx << 2));
            ull a0 = pack2(a.x, a.x), a1 = pack2(a.y, a.y);
            ull a2 = pack2(a.z, a.z), a3 = pack2(a.w, a.w);
            acc[0][0] = fma2(a0, bb.x, acc[0][0]); acc[0][1] = fma2(a0, bb.y, acc[0][1]);
            acc[1][0] = fma2(a1, bb.x, acc[1][0]); acc[1][1] = fma2(a1, bb.y, acc[1][1]);
            acc[2][0] = fma2(a2, bb.x, acc[2][0]); acc[2][1] = fma2(a2, bb.y, acc[2][1]);
            acc[3][0] = fma2(a3, bb.x, acc[3][0]); acc[3][1] = fma2(a3, bb.y, acc[3][1]);
        }
        if (t < 19) {
            float* An = sm + ((t + 1) & 1) * 2304;
            float* Bn = An + 1152;
            An[(a_c4 + 0) * 72 + a_r] = rA.x; An[(a_c4 + 1) * 72 + a_r] = rA.y;
            An[(a_c4 + 2) * 72 + a_r] = rA.z; An[(a_c4 + 3) * 72 + a_r] = rA.w;
            *(float4*)(Bn + b_r * 72 + b_c4) = rB;
        }
        __syncthreads();
    }
}

__global__ void __launch_bounds__(256) k_gemm(
    const float* __restrict__ Bin, const float* __restrict__ Csub,
    float* __restrict__ Cout, int ld, float alpha, float beta)
{
    __shared__ __align__(16) float sm[4608];
    int tid = threadIdx.x;
    int tx = tid & 15, ty = tid >> 4;
    int row0 = blockIdx.y << 6, col0 = blockIdx.x << 6;
    ull acc[4][2];
#pragma unroll
    for (int i = 0; i < 4; i++) { acc[i][0] = pack2(0.f, 0.f); acc[i][1] = pack2(0.f, 0.f); }
    gemm_mainloop_db(Bin, ld, row0, col0, sm, acc);
#pragma unroll
    for (int i = 0; i < 4; i++) {
        int row = row0 + (ty << 2) + i;
        float v[4];
        unpack2(acc[i][0], v[0], v[1]);
        unpack2(acc[i][1], v[2], v[3]);
        size_t o = (size_t)row * ld + col0 + (tx << 2);
        float4 cs = *(const float4*)(Csub + o);
        *(float4*)(Cout + o) = make_float4(
            alpha * v[0] + beta * cs.x, alpha * v[1] + beta * cs.y,
            alpha * v[2] + beta * cs.z, alpha * v[3] + beta * cs.w);
    }
}

// -------- combine: SB (+bf16 shadow) and SA ---------------------------------
__global__ void __launch_bounds__(128) k_combine(
    const float* __restrict__ cheb_w, const float* __restrict__ cheb_b,
    const float* __restrict__ cou_w, const float* __restrict__ Y,
    float* __restrict__ SA, float* __restrict__ SB,
    u16* __restrict__ SBhi, u16* __restrict__ SBlo)
{
    __shared__ float scw[KORD * CIN * HID];
    __shared__ float scb[HID];
    __shared__ float sco[CIN * HID];
    int tid = threadIdx.x;
    for (int i = tid; i < KORD * CIN * HID; i += 128) scw[i] = cheb_w[i];
    if (tid < HID) scb[tid] = cheb_b[tid];
    if (tid < CIN * HID) sco[tid] = cou_w[tid];
    __syncthreads();
    int idx = blockIdx.x * 128 + tid;
    if (idx >= NP * BATCH) return;
    int n = idx >> 9, b = idx & 511;
    size_t base = (size_t)n * BH + (b << 4);
    float o[16], p[16];
    if (n >= NNODE) {
#pragma unroll
        for (int h = 0; h < 16; h++) { o[h] = 0.f; p[h] = 0.f; }
    } else {
#pragma unroll
        for (int h = 0; h < 16; h++) { o[h] = scb[h]; p[h] = 0.f; }
#pragma unroll
        for (int k = 0; k < KORD; k++) {
#pragma unroll
            for (int c = 0; c < CIN; c++) {
                float y = Y[(size_t)k * NPBC + (size_t)n * BC + b * CIN + c];
                const float* w = &scw[(k * CIN + c) * HID];
#pragma unroll
                for (int h = 0; h < 16; h++) o[h] = fmaf(y, w[h], o[h]);
                if (k == 0) {
#pragma unroll
                    for (int h = 0; h < 16; h++) p[h] = fmaf(y, sco[c * HID + h], p[h]);
                }
            }
        }
    }
#pragma unroll
    for (int h = 0; h < 16; h++) { SB[base + h] = o[h]; SA[base + h] = p[h]; }
    u32* hiw = (u32*)(SBhi + base);
    u32* low = (u32*)(SBlo + base);
#pragma unroll
    for (int q = 0; q < 8; q++) {
        u32 hi, lo;
        split2(o[2 * q], o[2 * q + 1], hi, lo);
        hiw[q] = hi; low[q] = lo;
    }
}

// ======== GL via mma.sync bf16 split-precision, shadowed inputs =============
// Tile 64x64, 128 threads. K = 320 in 20 steps of 16.
// Stage (bytes): Ah[64x24]=3072, Al=3072, Bh[16x72]=2304, Bl=2304 -> 10752.
__global__ void __launch_bounds__(128) k_gl(
    const float* __restrict__ X,
    const u16* __restrict__ Xhi, const u16* __restrict__ Xlo,
    const float* __restrict__ A1, const float* __restrict__ A2,
    float* __restrict__ O1, float* __restrict__ O2,
    u16* __restrict__ Ohi, u16* __restrict__ Olo,
    const float* __restrict__ w1, const float* __restrict__ w2,
    const float* __restrict__ w3, const float* __restrict__ b3, int mode)
{
    __shared__ __align__(16) char smraw[21504];
    __shared__ float sw1[256], sw2[256], sw3[256], sb3[16];
    int tid = threadIdx.x;
    int lane = tid & 31, warp = tid >> 5;
    for (int i = tid; i < 256; i += 128) { sw1[i] = w1[i]; sw2[i] = w2[i]; sw3[i] = w3[i]; }
    if (tid < 16) sb3[tid] = b3[tid];

    const int ST = 10752;
    int m0 = blockIdx.y * 64, col0 = blockIdx.x * 64;

    float acc[8][4];
#pragma unroll
    for (int j = 0; j < 8; j++)
#pragma unroll
        for (int q = 0; q < 4; q++) acc[j][q] = 0.f;

    int a_row = tid >> 1, a_half = tid & 1;
    int b_row = tid >> 3, b_seg = tid & 7;
    const u16* Aph = g_Lhi + (size_t)(m0 + a_row) * NP + a_half * 8;
    const u16* Apl = g_Llo + (size_t)(m0 + a_row) * NP + a_half * 8;
    const u16* Bph = Xhi + (size_t)b_row * BH + col0 + b_seg * 8;
    const u16* Bpl = Xlo + (size_t)b_row * BH + col0 + b_seg * 8;
    u32 smbase = smem_u32(smraw);

    auto load_tile = [&](int kt, int st) {
        char* stg = smraw + st * ST;
        *(uint4*)(stg + a_row * 48 + a_half * 16) = *(const uint4*)(Aph + kt * 16);
        *(uint4*)(stg + 3072 + a_row * 48 + a_half * 16) = *(const uint4*)(Apl + kt * 16);
        size_t boff = (size_t)(kt * 16) * BH;
        *(uint4*)(stg + 6144 + b_row * 144 + b_seg * 16) = *(const uint4*)(Bph + boff);
        *(uint4*)(stg + 8448 + b_row * 144 + b_seg * 16) = *(const uint4*)(Bpl + boff);
    };

    load_tile(0, 0);
    __syncthreads();

#pragma unroll 1
    for (int t = 0; t < 20; t++) {
        int cur = t & 1;
        if (t < 19) load_tile(t + 1, cur ^ 1);
        u32 stg = smbase + cur * ST;
        u32 aoff = stg + (u32)((warp * 16 + (lane & 15)) * 48 + (lane >> 4) * 16);
        u32 ah[4], al[4];
        ldsm4(ah, aoff);
        ldsm4(al, aoff + 3072);
#pragma unroll
        for (int nt = 0; nt < 4; nt++) {
            u32 boff = stg + 6144 +
                (u32)((lane & 15) * 144 + (nt * 16 + ((lane >> 4) & 1) * 8) * 2);
            u32 bh[4], bl[4];
            ldsm4t(bh, boff);
            ldsm4t(bl, boff + 2304);
            hmma(acc[2 * nt],     ah, bh[0], bh[1]);
            hmma(acc[2 * nt],     ah, bl[0], bl[1]);
            hmma(acc[2 * nt],     al, bh[0], bh[1]);
            hmma(acc[2 * nt + 1], ah, bh[2], bh[3]);
            hmma(acc[2 * nt + 1], ah, bl[2], bl[3]);
            hmma(acc[2 * nt + 1], al, bh[2], bh[3]);
        }
        __syncthreads();
    }

    // stage o1 = L@X into smem (alias; stride 72 floats)
    float* o1s = (float*)smraw;
    {
        int r0 = warp * 16 + (lane >> 2);
        int c = (lane & 3) * 2;
#pragma unroll
        for (int j = 0; j < 8; j++) {
            *(float2*)&o1s[r0 * 72 + j * 8 + c]       = make_float2(acc[j][0], acc[j][1]);
            *(float2*)&o1s[(r0 + 8) * 72 + j * 8 + c] = make_float2(acc[j][2], acc[j][3]);
        }
    }
    __syncthreads();

    // epilogue: 256 items = 64 rows x 4 col-groups ; 2 per thread (f32x2 math)
#pragma unroll 1
    for (int it = 0; it < 2; it++) {
        int item = it * 128 + tid;
        int r = item >> 2, bl = item & 3;
        size_t base = (size_t)(m0 + r) * BH + col0 + (bl << 4);
        float xv[16];
#pragma unroll
        for (int q = 0; q < 4; q++) {
            float4 v = *(const float4*)(X + base + 4 * q);
            xv[4 * q] = v.x; xv[4 * q + 1] = v.y; xv[4 * q + 2] = v.z; xv[4 * q + 3] = v.w;
        }
        float a1v[16], a2v[16], rr[16], sv[16];
        {
            const ull* W2 = (const ull*)sw1;
            ull xs[16];
#pragma unroll
            for (int h = 0; h < 16; h++) xs[h] = pack2(xv[h], xv[h]);
#pragma unroll
            for (int pp = 0; pp < 8; pp++) {
                ull s = pack2(0.f, 0.f);
#pragma unroll
                for (int h = 0; h < 16; h++) s = fma2(xs[h], W2[h * 8 + pp], s);
                float s0, s1;
                unpack2(s, s0, s1);
                a1v[2 * pp] = ftanh(s0); a1v[2 * pp + 1] = ftanh(s1);
            }
        }
        {
            const ull* W2 = (const ull*)sw2;
            ull xs[16];
#pragma unroll
            for (int h = 0; h < 16; h++) xs[h] = pack2(a1v[h], a1v[h]);
#pragma unroll
            for (int pp = 0; pp < 8; pp++) {
                ull s = pack2(0.f, 0.f);
#pragma unroll
                for (int h = 0; h < 16; h++) s = fma2(xs[h], W2[h * 8 + pp], s);
                float s0, s1;
                unpack2(s, s0, s1);
                a2v[2 * pp] = ftanh(s0); a2v[2 * pp + 1] = ftanh(s1);
            }
        }
        const float* o1p = o1s + r * 72 + (bl << 4);
#pragma unroll
        for (int h = 0; h < 16; h++) rr[h] = o1p[h] - a2v[h];
        {
            const ull* W2 = (const ull*)sw3;
            const ull* b2 = (const ull*)sb3;
            ull xs[16];
#pragma unroll
            for (int h = 0; h < 16; h++) xs[h] = pack2(rr[h], rr[h]);
#pragma unroll
            for (int pp = 0; pp < 8; pp++) {
                ull s = b2[pp];
#pragma unroll
                for (int h = 0; h < 16; h++) s = fma2(xs[h], W2[h * 8 + pp], s);
                unpack2(s, sv[2 * pp], sv[2 * pp + 1]);
            }
        }
        float ov[16];
        if (mode == 0) {
#pragma unroll
            for (int p = 0; p < 16; p++) {
                O1[base + p] = sv[p];
                ov[p] = A1[base + p] + 2.0f * sv[p];
                O2[base + p] = ov[p];
            }
        } else {
#pragma unroll
            for (int p = 0; p < 16; p++) {
                ov[p] = A1[base + p] + 0.5f * A2[base + p] + 0.5f * sv[p];
                O1[base + p] = ov[p];
            }
        }
        u32* hiw = (u32*)(Ohi + base);
        u32* low = (u32*)(Olo + base);
#pragma unroll
        for (int q = 0; q < 8; q++) {
            u32 hi, lo;
            split2(ov[2 * q], ov[2 * q + 1], hi, lo);
            hiw[q] = hi; low[q] = lo;
        }
    }
}

// ---------------- 16x16 matmul helper with f32x2 ----------------------------
__device__ __forceinline__ void mm16_f2(const float* x, const float* Wsh,
                                        const ull* bias2, float* out)
{
    const ull* W2 = (const ull*)Wsh;
    ull xs[16];
#pragma unroll
    for (int h = 0; h < 16; h++) xs[h] = pack2(x[h], x[h]);
#pragma unroll
    for (int pp = 0; pp < 8; pp++) {
        ull s = bias2 ? bias2[pp] : pack2(0.f, 0.f);
#pragma unroll
        for (int h = 0; h < 16; h++) s = fma2(xs[h], W2[h * 8 + pp], s);
        unpack2(s, out[2 * pp], out[2 * pp + 1]);
    }
}

// ---------------- NL: fused 10-step LSTM-cell chain (f32x2) -----------------
__device__ __forceinline__ void nl_eval(
    const float* x, float* out,
    const ull* W2, const ull* sb2, const ull* w22)
{
    ull xs[16];
#pragma unroll
    for (int h = 0; h < 16; h++) xs[h] = pack2(x[h], x[h]);
    ull acc2[8];
#pragma unroll
    for (int q = 0; q < 8; q++) acc2[q] = pack2(0.f, 0.f);
#pragma unroll 1
    for (int pp = 0; pp < 16; pp++) {
        ull gi = sb2[pp], gg = sb2[32 + pp], go = sb2[48 + pp];
#pragma unroll
        for (int h = 0; h < 16; h++) {
            gi = fma2(xs[h], W2[h * 64 + pp], gi);
            gg = fma2(xs[h], W2[h * 64 + 32 + pp], gg);
            go = fma2(xs[h], W2[h * 64 + 48 + pp], go);
        }
        float gi0, gi1, gg0, gg1, go0, go1;
        unpack2(gi, gi0, gi1); unpack2(gg, gg0, gg1); unpack2(go, go0, go1);
        float c0 = fsig(gi0) * ftanh(gg0);
        float th0 = ftanh(fsig(go0) * ftanh(c0));
        float c1 = fsig(gi1) * ftanh(gg1);
        float th1 = ftanh(fsig(go1) * ftanh(c1));
        ull t0 = pack2(th0, th0), t1 = pack2(th1, th1);
#pragma unroll
        for (int q = 0; q < 8; q++) {
            acc2[q] = fma2(t0, w22[(2 * pp) * 8 + q], acc2[q]);
            acc2[q] = fma2(t1, w22[(2 * pp + 1) * 8 + q], acc2[q]);
        }
    }
#pragma unroll
    for (int q = 0; q < 8; q++) unpack2(acc2[q], out[2 * q], out[2 * q + 1]);
}

__global__ void __launch_bounds__(128) k_nl(
    const float* __restrict__ S0, const float* __restrict__ S1,
    const float* __restrict__ Wih, const float* __restrict__ lb,
    const float* __restrict__ w2, const float* __restrict__ cw,
    const float* __restrict__ cb, const float* __restrict__ c1w,
    const float* __restrict__ c1b, float* __restrict__ out)
{
    __shared__ __align__(16) float sW[16 * 128];
    __shared__ __align__(16) float sb[128];
    __shared__ __align__(16) float sw2[32 * 16];
    __shared__ __align__(16) float scw[256], sc1w[256];
    __shared__ __align__(16) float scb[16], sc1b[16];
    int tid = threadIdx.x;
    for (int i = tid; i < 2048; i += 128) sW[i] = Wih[i];
    sb[tid] = lb[tid];
    for (int i = tid; i < 512; i += 128) sw2[i] = w2[i];
    for (int i = tid; i < 256; i += 128) { scw[i] = cw[i]; sc1w[i] = c1w[i]; }
    if (tid < 16) { scb[tid] = cb[tid]; sc1b[tid] = c1b[tid]; }
    __syncthreads();
    const ull* W2  = (const ull*)sW;
    const ull* sb2 = (const ull*)sb;
    const ull* w22 = (const ull*)sw2;

    int idx = blockIdx.x * 128 + tid;
    int n = idx >> 9, b = idx & 511;
    size_t base = (size_t)n * BH + ((size_t)b << 4);
    float s0[16], s1[16];
#pragma unroll
    for (int q = 0; q < 4; q++) {
        float4 t0 = *(const float4*)(S0 + base + 4 * q);
        float4 t1 = *(const float4*)(S1 + base + 4 * q);
        s0[4 * q] = t0.x; s0[4 * q + 1] = t0.y; s0[4 * q + 2] = t0.z; s0[4 * q + 3] = t0.w;
        s1[4 * q] = t1.x; s1[4 * q + 1] = t1.y; s1[4 * q + 2] = t1.z; s1[4 * q + 3] = t1.w;
    }
    float s00[16], s11[16];
    mm16_f2(s0, scw, (const ull*)scb, s00);
    mm16_f2(s1, sc1w, (const ull*)sc1b, s11);
    float* op = out + (((size_t)b * NNODE + n) * 10) * HID;
    float t[16], tmp[16], g[16], p2[16];
    nl_eval(s11, t, W2, sb2, w22);
#pragma unroll
    for (int h = 0; h < 16; h++) tmp[h] = fmaf(2.0f, t[h], s00[h]);
    nl_eval(tmp, tmp, W2, sb2, w22);
#pragma unroll
    for (int h = 0; h < 16; h++) {
        g[h] = fmaf(0.5f, t[h], s1[h]) + 0.5f * tmp[h];
        p2[h] = s11[h];
    }
#pragma unroll
    for (int q = 0; q < 4; q++)
        *(float4*)(op + 4 * q) = make_float4(g[4 * q], g[4 * q + 1], g[4 * q + 2], g[4 * q + 3]);
#pragma unroll 1
    for (int j = 1; j < 10; j++) {
        nl_eval(g, t, W2, sb2, w22);
#pragma unroll
        for (int h = 0; h < 16; h++) tmp[h] = fmaf(2.0f, t[h], p2[h]);
        nl_eval(tmp, tmp, W2, sb2, w22);
#pragma unroll
        for (int h = 0; h < 16; h++) {
            float nw = fmaf(0.5f, t[h], g[h]) + 0.5f * tmp[h];
            p2[h] = g[h];
            g[h] = nw;
        }
        float* oj = op + (size_t)j * HID;
#pragma unroll
        for (int q = 0; q < 4; q++)
            *(float4*)(oj + 4 * q) = make_float4(g[4 * q], g[4 * q + 1], g[4 * q + 2], g[4 * q + 3]);
    }
}

// ------------------------------ launch --------------------------------------
extern "C" void kernel_launch(void* const* d_in, const int* in_sizes, int n_in,
                              void* d_out, int out_size) {
    const float* flow    = (const float*)d_in[0];
    const float* nodeemb = (const float*)d_in[1];
    const float* cheb_w  = (const float*)d_in[2];
    const float* cheb_b  = (const float*)d_in[3];
    const float* cou_w   = (const float*)d_in[4];
    const float* gl_out  = (const float*)d_in[5];
    const float* gl_fk   = (const float*)d_in[6];
    const float* gl_tz_w = (const float*)d_in[7];
    const float* gl_tz_b = (const float*)d_in[8];
    const float* lstmW   = (const float*)d_in[9];
    const float* lstmb   = (const float*)d_in[10];
    const float* nl_w2   = (const float*)d_in[11];
    const float* c_w     = (const float*)d_in[12];
    const float* c_b     = (const float*)d_in[13];
    const float* c1_w    = (const float*)d_in[14];
    const float* c1_b    = (const float*)d_in[15];

    float *Y, *SA, *SB, *T, *U;
    u16 *HAhi, *HAlo, *HBhi, *HBlo, *HUhi, *HUlo;
    cudaGetSymbolAddress((void**)&Y,  g_Y);
    cudaGetSymbolAddress((void**)&SA, g_SA);
    cudaGetSymbolAddress((void**)&SB, g_SB);
    cudaGetSymbolAddress((void**)&T,  g_T);
    cudaGetSymbolAddress((void**)&U,  g_U);
    cudaGetSymbolAddress((void**)&HAhi, g_HAhi);
    cudaGetSymbolAddress((void**)&HAlo, g_HAlo);
    cudaGetSymbolAddress((void**)&HBhi, g_HBhi);
    cudaGetSymbolAddress((void**)&HBlo, g_HBlo);
    cudaGetSymbolAddress((void**)&HUhi, g_HUhi);
    cudaGetSymbolAddress((void**)&HUlo, g_HUlo);

    k_xt<<<(NP * BATCH + 127) / 128, 128>>>(flow, Y);
    k_norm<<<1, 320>>>(nodeemb);
    k_lap<<<(NP * NP + 255) / 256, 256>>>();

    // Chebyshev feature recurrence (fp32 path)
    k_gemm<<<dim3(BC / 64, NP / 64), 256>>>(Y, Y, Y + NPBC, BC, 1.f, 0.f);
    for (int k = 2; k < KORD; k++)
        k_gemm<<<dim3(BC / 64, NP / 64), 256>>>(
            Y + (size_t)(k - 1) * NPBC, Y + (size_t)(k - 2) * NPBC,
            Y + (size_t)k * NPBC, BC, 2.f, -1.f);

    k_combine<<<(NP * BATCH + 127) / 128, 128>>>(cheb_w, cheb_b, cou_w, Y,
                                                 SA, SB, HBhi, HBlo);

    // GL diffusion chain (HMMA path with bf16 shadows)
    float* p = SA;  u16* pHi = HAhi; u16* pLo = HAlo;
    float* c = SB;  u16* cHi = HBhi; u16* cLo = HBlo;
    dim3 glgrid(BH / 64, NP / 64);
    for (int it = 0; it < 10; it++) {
        // mode 0: X = c, outputs T (=GL(c)) and U (=p + 2T, shadowed)
        k_gl<<<glgrid, 128>>>(c, cHi, cLo, p, p, T, U, HUhi, HUlo,
                              gl_out, gl_fk, gl_tz_w, gl_tz_b, 0);
        // mode 1: X = U, output -> p buffer (shadowed)
        k_gl<<<glgrid, 128>>>(U, HUhi, HUlo, c, T, p, T, pHi, pLo,
                              gl_out, gl_fk, gl_tz_w, gl_tz_b, 1);
        float* tf = p; p = c; c = tf;
        u16* th = pHi; pHi = cHi; cHi = th;
        u16* tl = pLo; pLo = cLo; cLo = tl;
    }
    // after 10 iters: step_0 = p, step_1 = c

    k_nl<<<(NNODE * BATCH) / 128, 128>>>(p, c, lstmW, lstmb, nl_w2,
                                         c_w, c_b, c1_w, c1_b, (float*)d_out);
}

// round 14
// speedup vs baseline: 2.3005x; 2.3005x over previous
#include <cuda_runtime.h>
#include <math.h>
#include <stdint.h>

typedef unsigned long long ull;
typedef unsigned int u32;
typedef unsigned short u16;

#define NNODE 307
#define NP    320
#define BATCH 512
#define CIN   5
#define HID   16
#define KORD  6
#define BH    8192          // BATCH*HID
#define BC    2560          // BATCH*CIN
#define NPBC  (NP*BC)

// ------------------------------ scratch ------------------------------------
__device__ __align__(256) float g_En[NNODE * 10];
__device__ __align__(256) float g_dinv[NNODE];
__device__ __align__(256) float g_L[NP * NP];
__device__ __align__(256) u16 g_Lhi[NP * NP];
__device__ __align__(256) u16 g_Llo[NP * NP];
__device__ __align__(256) float g_Y[KORD * NPBC];
__device__ __align__(256) float g_SA[NP * BH];
__device__ __align__(256) float g_SB[NP * BH];
__device__ __align__(256) float g_T[NP * BH];
__device__ __align__(256) float g_U[NP * BH];

// ------------------------------ helpers ------------------------------------
__device__ __forceinline__ ull pack2(float x, float y) {
    ull d; asm("mov.b64 %0, {%1, %2};" : "=l"(d) : "f"(x), "f"(y)); return d;
}
__device__ __forceinline__ void unpack2(ull v, float& x, float& y) {
    asm("mov.b64 {%0, %1}, %2;" : "=f"(x), "=f"(y) : "l"(v));
}
__device__ __forceinline__ ull fma2(ull a, ull b, ull c) {
    ull d; asm("fma.rn.f32x2 %0, %1, %2, %3;" : "=l"(d) : "l"(a), "l"(b), "l"(c));
    return d;
}
__device__ __forceinline__ float ftanh(float x) {
    float e; asm("ex2.approx.f32 %0, %1;" : "=f"(e) : "f"(x * 2.885390082f));
    float r; asm("rcp.approx.f32 %0, %1;" : "=f"(r) : "f"(e + 1.0f));
    return fmaf(-2.0f, r, 1.0f);
}
__device__ __forceinline__ float fsig(float x) {
    return fmaf(0.5f, ftanh(0.5f * x), 0.5f);
}
__device__ __forceinline__ u32 smem_u32(const void* p) {
    u32 a;
    asm("{ .reg .u64 t; cvta.to.shared.u64 t, %1; cvt.u32.u64 %0, t; }"
        : "=r"(a) : "l"(p));
    return a;
}
__device__ __forceinline__ void hmma(float* d, const u32* a, u32 b0, u32 b1) {
    asm volatile("mma.sync.aligned.m16n8k16.row.col.f32.bf16.bf16.f32 "
        "{%0,%1,%2,%3}, {%4,%5,%6,%7}, {%8,%9}, {%0,%1,%2,%3};"
        : "+f"(d[0]), "+f"(d[1]), "+f"(d[2]), "+f"(d[3])
        : "r"(a[0]), "r"(a[1]), "r"(a[2]), "r"(a[3]), "r"(b0), "r"(b1));
}
__device__ __forceinline__ void ldsm4(u32* r, u32 addr) {
    asm volatile("ldmatrix.sync.aligned.m8n8.x4.shared.b16 {%0,%1,%2,%3}, [%4];"
        : "=r"(r[0]), "=r"(r[1]), "=r"(r[2]), "=r"(r[3]) : "r"(addr));
}
__device__ __forceinline__ void ldsm4t(u32* r, u32 addr) {
    asm volatile("ldmatrix.sync.aligned.m8n8.x4.trans.shared.b16 {%0,%1,%2,%3}, [%4];"
        : "=r"(r[0]), "=r"(r[1]), "=r"(r[2]), "=r"(r[3]) : "r"(addr));
}

// ------------------------------ setup ---------------------------------------
__global__ void __launch_bounds__(320) k_norm(const float* __restrict__ E) {
    __shared__ float sSum[10];
    int t = threadIdx.x;
    if (t < 10) sSum[t] = 0.f;
    __syncthreads();
    float e[10];
    if (t < NNODE) {
        float s = 0.f;
#pragma unroll
        for (int c = 0; c < 10; c++) { e[c] = E[t * 10 + c]; s += e[c] * e[c]; }
        float inv = rsqrtf(s);
#pragma unroll
        for (int c = 0; c < 10; c++) {
            e[c] *= inv;
            g_En[t * 10 + c] = e[c];
            atomicAdd(&sSum[c], e[c]);
        }
    }
    __syncthreads();
    if (t < NNODE) {
        float d = 0.f;
#pragma unroll
        for (int c = 0; c < 10; c++) d += e[c] * sSum[c];
        g_dinv[t] = rsqrtf(d);
    }
}

__global__ void k_lap() {
    int idx = blockIdx.x * 256 + threadIdx.x;
    if (idx >= NP * NP) return;
    int n = idx / NP, m = idx % NP;
    float v = 0.f;
    if (n < NNODE && m < NNODE) {
        float dot = 0.f;
#pragma unroll
        for (int c = 0; c < 10; c++) dot += g_En[n * 10 + c] * g_En[m * 10 + c];
        v = ((n == m) ? 1.f : 0.f) - g_dinv[n] * dot * g_dinv[m];
    }
    g_L[idx] = v;
    u32 bits = __float_as_uint(v);
    float res = v - __uint_as_float(bits & 0xFFFF0000u);
    u16 lo16;
    asm("cvt.rn.bf16.f32 %0, %1;" : "=h"(lo16) : "f"(res));
    g_Lhi[idx] = (u16)(bits >> 16);
    g_Llo[idx] = lo16;
}

__global__ void k_xt(const float* __restrict__ flow, float* __restrict__ Y0) {
    int idx = blockIdx.x * 128 + threadIdx.x;
    if (idx >= NP * BATCH) return;
    int n = idx >> 9, b = idx & 511;
#pragma unroll
    for (int c = 0; c < CIN; c++) {
        float v = 0.f;
        if (n < NNODE) v = flow[((size_t)b * NNODE + n) * CIN + c];
        Y0[(size_t)n * BC + b * CIN + c] = v;
    }
}

// ====== shared HMMA split-precision mainloop: 64x64 tile, 128 threads =======
// Stage (bytes): Ah[64x24]=3072, Al=3072, Bh[16x72]=2304, Bl=2304 -> 10752.
// B is fp32 (split on the fly), A is precomputed g_Lhi/g_Llo.
#define HMMA_ST 10752
__device__ __forceinline__ void hmma_mainloop(
    const float* __restrict__ Bsrc, int ld, int m0, int col0,
    char* smraw, float acc[8][4])
{
    int tid = threadIdx.x;
    int lane = tid & 31, warp = tid >> 5;
    int a_row = tid >> 1, a_half = tid & 1;
    int b_row = tid >> 3, b_seg = tid & 7;
    const u16* Aph = g_Lhi + (size_t)(m0 + a_row) * NP + a_half * 8;
    const u16* Apl = g_Llo + (size_t)(m0 + a_row) * NP + a_half * 8;
    const float* Bp = Bsrc + (size_t)b_row * ld + col0 + b_seg * 8;
    u32 smbase = smem_u32(smraw);

    auto load_tile = [&](int kt, int st) {
        char* stg = smraw + st * HMMA_ST;
        *(uint4*)(stg + a_row * 48 + a_half * 16) = *(const uint4*)(Aph + kt * 16);
        *(uint4*)(stg + 3072 + a_row * 48 + a_half * 16) = *(const uint4*)(Apl + kt * 16);
        const float* bp = Bp + (size_t)(kt * 16) * ld;
        float4 f0 = ((const float4*)bp)[0];
        float4 f1 = ((const float4*)bp)[1];
        float f[8] = {f0.x, f0.y, f0.z, f0.w, f1.x, f1.y, f1.z, f1.w};
        u32 hi[4], lo[4];
#pragma unroll
        for (int q = 0; q < 4; q++) {
            u32 ba = __float_as_uint(f[2 * q]);
            u32 bb = __float_as_uint(f[2 * q + 1]);
            asm("prmt.b32 %0, %1, %2, 0x7632;" : "=r"(hi[q]) : "r"(ba), "r"(bb));
            float ra = f[2 * q]     - __uint_as_float(ba & 0xFFFF0000u);
            float rb = f[2 * q + 1] - __uint_as_float(bb & 0xFFFF0000u);
            asm("cvt.rn.bf16x2.f32 %0, %1, %2;" : "=r"(lo[q]) : "f"(rb), "f"(ra));
        }
        *(uint4*)(stg + 6144 + b_row * 144 + b_seg * 16) = make_uint4(hi[0], hi[1], hi[2], hi[3]);
        *(uint4*)(stg + 8448 + b_row * 144 + b_seg * 16) = make_uint4(lo[0], lo[1], lo[2], lo[3]);
    };

    load_tile(0, 0);
    __syncthreads();

#pragma unroll 1
    for (int t = 0; t < 20; t++) {
        int cur = t & 1;
        if (t < 19) load_tile(t + 1, cur ^ 1);
        u32 stg = smbase + cur * HMMA_ST;
        u32 aoff = stg + (u32)((warp * 16 + (lane & 15)) * 48 + (lane >> 4) * 16);
        u32 ah[4], al[4];
        ldsm4(ah, aoff);
        ldsm4(al, aoff + 3072);
#pragma unroll
        for (int nt = 0; nt < 4; nt++) {
            u32 boff = stg + 6144 +
                (u32)((lane & 15) * 144 + (nt * 16 + ((lane >> 4) & 1) * 8) * 2);
            u32 bh[4], bl[4];
            ldsm4t(bh, boff);
            ldsm4t(bl, boff + 2304);
            hmma(acc[2 * nt],     ah, bh[0], bh[1]);
            hmma(acc[2 * nt],     ah, bl[0], bl[1]);
            hmma(acc[2 * nt],     al, bh[0], bh[1]);
            hmma(acc[2 * nt + 1], ah, bh[2], bh[3]);
            hmma(acc[2 * nt + 1], ah, bl[2], bl[3]);
            hmma(acc[2 * nt + 1], al, bh[2], bh[3]);
        }
        __syncthreads();
    }
}

// ---- cheb: Cout = alpha*(L@Bin) + beta*Csub, HMMA path ---------------------
__global__ void __launch_bounds__(128) k_mm(
    const float* __restrict__ Bin, const float* __restrict__ Csub,
    float* __restrict__ Cout, int ld, float alpha, float beta)
{
    __shared__ __align__(16) char smraw[21504];
    int tid = threadIdx.x;
    int lane = tid & 31, warp = tid >> 5;
    int m0 = blockIdx.y * 64, col0 = blockIdx.x * 64;
    float acc[8][4];
#pragma unroll
    for (int j = 0; j < 8; j++)
#pragma unroll
        for (int q = 0; q < 4; q++) acc[j][q] = 0.f;
    hmma_mainloop(Bin, ld, m0, col0, smraw, acc);

    int r0 = m0 + warp * 16 + (lane >> 2);
    int c0 = col0 + (lane & 3) * 2;
#pragma unroll
    for (int j = 0; j < 8; j++) {
        size_t oa = (size_t)r0 * ld + c0 + j * 8;
        size_t ob = (size_t)(r0 + 8) * ld + c0 + j * 8;
        float2 ca = *(const float2*)(Csub + oa);
        float2 cb = *(const float2*)(Csub + ob);
        *(float2*)(Cout + oa) = make_float2(alpha * acc[j][0] + beta * ca.x,
                                            alpha * acc[j][1] + beta * ca.y);
        *(float2*)(Cout + ob) = make_float2(alpha * acc[j][2] + beta * cb.x,
                                            alpha * acc[j][3] + beta * cb.y);
    }
}

// -------- combine: SB = sum_k Y_k @ cheb_w[k] + cheb_b ; SA = Y_0 @ cou_w ---
__global__ void __launch_bounds__(128) k_combine(
    const float* __restrict__ cheb_w, const float* __restrict__ cheb_b,
    const float* __restrict__ cou_w, const float* __restrict__ Y,
    float* __restrict__ SA, float* __restrict__ SB)
{
    __shared__ float scw[KORD * CIN * HID];
    __shared__ float scb[HID];
    __shared__ float sco[CIN * HID];
    int tid = threadIdx.x;
    for (int i = tid; i < KORD * CIN * HID; i += 128) scw[i] = cheb_w[i];
    if (tid < HID) scb[tid] = cheb_b[tid];
    if (tid < CIN * HID) sco[tid] = cou_w[tid];
    __syncthreads();
    int idx = blockIdx.x * 128 + tid;
    if (idx >= NP * BATCH) return;
    int n = idx >> 9, b = idx & 511;
    size_t base = (size_t)n * BH + (b << 4);
    if (n >= NNODE) {
#pragma unroll
        for (int h = 0; h < 16; h++) { SA[base + h] = 0.f; SB[base + h] = 0.f; }
        return;
    }
    float o[16], p[16];
#pragma unroll
    for (int h = 0; h < 16; h++) { o[h] = scb[h]; p[h] = 0.f; }
#pragma unroll
    for (int k = 0; k < KORD; k++) {
#pragma unroll
        for (int c = 0; c < CIN; c++) {
            float y = Y[(size_t)k * NPBC + (size_t)n * BC + b * CIN + c];
            const float* w = &scw[(k * CIN + c) * HID];
#pragma unroll
            for (int h = 0; h < 16; h++) o[h] = fmaf(y, w[h], o[h]);
            if (k == 0) {
#pragma unroll
                for (int h = 0; h < 16; h++) p[h] = fmaf(y, sco[c * HID + h], p[h]);
            }
        }
    }
#pragma unroll
    for (int h = 0; h < 16; h++) { SB[base + h] = o[h]; SA[base + h] = p[h]; }
}

// ======== GL via mma.sync bf16 split-precision (R12-exact) ==================
__global__ void __launch_bounds__(128) k_gl(
    const float* __restrict__ X, const float* __restrict__ A1,
    const float* __restrict__ A2,
    float* __restrict__ O1, float* __restrict__ O2,
    const float* __restrict__ w1, const float* __restrict__ w2,
    const float* __restrict__ w3, const float* __restrict__ b3, int mode)
{
    __shared__ __align__(16) char smraw[21504];
    __shared__ float sw1[256], sw2[256], sw3[256], sb3[16];
    int tid = threadIdx.x;
    int lane = tid & 31, warp = tid >> 5;
    for (int i = tid; i < 256; i += 128) { sw1[i] = w1[i]; sw2[i] = w2[i]; sw3[i] = w3[i]; }
    if (tid < 16) sb3[tid] = b3[tid];

    int m0 = blockIdx.y * 64, col0 = blockIdx.x * 64;
    float acc[8][4];
#pragma unroll
    for (int j = 0; j < 8; j++)
#pragma unroll
        for (int q = 0; q < 4; q++) acc[j][q] = 0.f;
    hmma_mainloop(X, BH, m0, col0, smraw, acc);

    // stage o1 = L@X into smem (alias; stride 72 floats)
    float* o1s = (float*)smraw;
    {
        int r0 = warp * 16 + (lane >> 2);
        int c = (lane & 3) * 2;
#pragma unroll
        for (int j = 0; j < 8; j++) {
            *(float2*)&o1s[r0 * 72 + j * 8 + c]       = make_float2(acc[j][0], acc[j][1]);
            *(float2*)&o1s[(r0 + 8) * 72 + j * 8 + c] = make_float2(acc[j][2], acc[j][3]);
        }
    }
    __syncthreads();

    // epilogue: 256 items = 64 rows x 4 col-groups ; 2 per thread
#pragma unroll 1
    for (int it = 0; it < 2; it++) {
        int item = it * 128 + tid;
        int r = item >> 2, bl = item & 3;
        size_t base = (size_t)(m0 + r) * BH + col0 + (bl << 4);
        float xv[16];
#pragma unroll
        for (int q = 0; q < 4; q++) {
            float4 v = *(const float4*)(X + base + 4 * q);
            xv[4 * q] = v.x; xv[4 * q + 1] = v.y; xv[4 * q + 2] = v.z; xv[4 * q + 3] = v.w;
        }
        float a1v[16];
#pragma unroll 4
        for (int p = 0; p < 16; p++) {
            float s = 0.f;
#pragma unroll
            for (int h = 0; h < 16; h++) s = fmaf(xv[h], sw1[h * 16 + p], s);
            a1v[p] = ftanh(s);
        }
        float a2v[16];
#pragma unroll 4
        for (int p = 0; p < 16; p++) {
            float s = 0.f;
#pragma unroll
            for (int h = 0; h < 16; h++) s = fmaf(a1v[h], sw2[h * 16 + p], s);
            a2v[p] = ftanh(s);
        }
        float rr[16];
        const float* o1p = o1s + r * 72 + (bl << 4);
#pragma unroll
        for (int h = 0; h < 16; h++) rr[h] = o1p[h] - a2v[h];
        if (mode == 0) {
#pragma unroll 4
            for (int p = 0; p < 16; p++) {
                float s = sb3[p];
#pragma unroll
                for (int h = 0; h < 16; h++) s = fmaf(rr[h], sw3[h * 16 + p], s);
                O1[base + p] = s;
                O2[base + p] = A1[base + p] + 2.0f * s;
            }
        } else {
#pragma unroll 4
            for (int p = 0; p < 16; p++) {
                float s = sb3[p];
#pragma unroll
                for (int h = 0; h < 16; h++) s = fmaf(rr[h], sw3[h * 16 + p], s);
                O1[base + p] = A1[base + p] + 0.5f * A2[base + p] + 0.5f * s;
            }
        }
    }
}

// ---------------- 16x16 matmul helper with f32x2 ----------------------------
__device__ __forceinline__ void mm16_f2(const float* x, const float* Wsh,
                                        const ull* bias2, float* out)
{
    const ull* W2 = (const ull*)Wsh;
    ull xs[16];
#pragma unroll
    for (int h = 0; h < 16; h++) xs[h] = pack2(x[h], x[h]);
#pragma unroll
    for (int pp = 0; pp < 8; pp++) {
        ull s = bias2 ? bias2[pp] : pack2(0.f, 0.f);
#pragma unroll
        for (int h = 0; h < 16; h++) s = fma2(xs[h], W2[h * 8 + pp], s);
        unpack2(s, out[2 * pp], out[2 * pp + 1]);
    }
}

// ---------------- NL: fused 10-step LSTM-cell chain (f32x2) -----------------
__device__ __forceinline__ void nl_eval(
    const float* x, float* out,
    const ull* W2, const ull* sb2, const ull* w22)
{
    ull xs[16];
#pragma unroll
    for (int h = 0; h < 16; h++) xs[h] = pack2(x[h], x[h]);
    ull acc2[8];
#pragma unroll
    for (int q = 0; q < 8; q++) acc2[q] = pack2(0.f, 0.f);
#pragma unroll 1
    for (int pp = 0; pp < 16; pp++) {
        ull gi = sb2[pp], gg = sb2[32 + pp], go = sb2[48 + pp];
#pragma unroll
        for (int h = 0; h < 16; h++) {
            gi = fma2(xs[h], W2[h * 64 + pp], gi);
            gg = fma2(xs[h], W2[h * 64 + 32 + pp], gg);
            go = fma2(xs[h], W2[h * 64 + 48 + pp], go);
        }
        float gi0, gi1, gg0, gg1, go0, go1;
        unpack2(gi, gi0, gi1); unpack2(gg, gg0, gg1); unpack2(go, go0, go1);
        float c0 = fsig(gi0) * ftanh(gg0);
        float th0 = ftanh(fsig(go0) * ftanh(c0));
        float c1 = fsig(gi1) * ftanh(gg1);
        float th1 = ftanh(fsig(go1) * ftanh(c1));
        ull t0 = pack2(th0, th0), t1 = pack2(th1, th1);
#pragma unroll
        for (int q = 0; q < 8; q++) {
            acc2[q] = fma2(t0, w22[(2 * pp) * 8 + q], acc2[q]);
            acc2[q] = fma2(t1, w22[(2 * pp + 1) * 8 + q], acc2[q]);
        }
    }
#pragma unroll
    for (int q = 0; q < 8; q++) unpack2(acc2[q], out[2 * q], out[2 * q + 1]);
}

__global__ void __launch_bounds__(128) k_nl(
    const float* __restrict__ S0, const float* __restrict__ S1,
    const float* __restrict__ Wih, const float* __restrict__ lb,
    const float* __restrict__ w2, const float* __restrict__ cw,
    const float* __restrict__ cb, const float* __restrict__ c1w,
    const float* __restrict__ c1b, float* __restrict__ out)
{
    __shared__ __align__(16) float sW[16 * 128];
    __shared__ __align__(16) float sb[128];
    __shared__ __align__(16) float sw2[32 * 16];
    __shared__ __align__(16) float scw[256], sc1w[256];
    __shared__ __align__(16) float scb[16], sc1b[16];
    int tid = threadIdx.x;
    for (int i = tid; i < 2048; i += 128) sW[i] = Wih[i];
    sb[tid] = lb[tid];
    for (int i = tid; i < 512; i += 128) sw2[i] = w2[i];
    for (int i = tid; i < 256; i += 128) { scw[i] = cw[i]; sc1w[i] = c1w[i]; }
    if (tid < 16) { scb[tid] = cb[tid]; sc1b[tid] = c1b[tid]; }
    __syncthreads();
    const ull* W2  = (const ull*)sW;
    const ull* sb2 = (const ull*)sb;
    const ull* w22 = (const ull*)sw2;

    int idx = blockIdx.x * 128 + tid;
    int n = idx >> 9, b = idx & 511;
    size_t base = (size_t)n * BH + ((size_t)b << 4);
    float s0[16], s1[16];
#pragma unroll
    for (int q = 0; q < 4; q++) {
        float4 t0 = *(const float4*)(S0 + base + 4 * q);
        float4 t1 = *(const float4*)(S1 + base + 4 * q);
        s0[4 * q] = t0.x; s0[4 * q + 1] = t0.y; s0[4 * q + 2] = t0.z; s0[4 * q + 3] = t0.w;
        s1[4 * q] = t1.x; s1[4 * q + 1] = t1.y; s1[4 * q + 2] = t1.z; s1[4 * q + 3] = t1.w;
    }
    float s00[16], s11[16];
    mm16_f2(s0, scw, (const ull*)scb, s00);
    mm16_f2(s1, sc1w, (const ull*)sc1b, s11);
    float* op = out + (((size_t)b * NNODE + n) * 10) * HID;
    float t[16], tmp[16], g[16], p2[16];
    nl_eval(s11, t, W2, sb2, w22);
#pragma unroll
    for (int h = 0; h < 16; h++) tmp[h] = fmaf(2.0f, t[h], s00[h]);
    nl_eval(tmp, tmp, W2, sb2, w22);
#pragma unroll
    for (int h = 0; h < 16; h++) {
        g[h] = fmaf(0.5f, t[h], s1[h]) + 0.5f * tmp[h];
        p2[h] = s11[h];
    }
#pragma unroll
    for (int q = 0; q < 4; q++)
        *(float4*)(op + 4 * q) = make_float4(g[4 * q], g[4 * q + 1], g[4 * q + 2], g[4 * q + 3]);
#pragma unroll 1
    for (int j = 1; j < 10; j++) {
        nl_eval(g, t, W2, sb2, w22);
#pragma unroll
        for (int h = 0; h < 16; h++) tmp[h] = fmaf(2.0f, t[h], p2[h]);
        nl_eval(tmp, tmp, W2, sb2, w22);
#pragma unroll
        for (int h = 0; h < 16; h++) {
            float nw = fmaf(0.5f, t[h], g[h]) + 0.5f * tmp[h];
            p2[h] = g[h];
            g[h] = nw;
        }
        float* oj = op + (size_t)j * HID;
#pragma unroll
        for (int q = 0; q < 4; q++)
            *(float4*)(oj + 4 * q) = make_float4(g[4 * q], g[4 * q + 1], g[4 * q + 2], g[4 * q + 3]);
    }
}

// ------------------------------ launch --------------------------------------
extern "C" void kernel_launch(void* const* d_in, const int* in_sizes, int n_in,
                              void* d_out, int out_size) {
    const float* flow    = (const float*)d_in[0];
    const float* nodeemb = (const float*)d_in[1];
    const float* cheb_w  = (const float*)d_in[2];
    const float* cheb_b  = (const float*)d_in[3];
    const float* cou_w   = (const float*)d_in[4];
    const float* gl_out  = (const float*)d_in[5];
    const float* gl_fk   = (const float*)d_in[6];
    const float* gl_tz_w = (const float*)d_in[7];
    const float* gl_tz_b = (const float*)d_in[8];
    const float* lstmW   = (const float*)d_in[9];
    const float* lstmb   = (const float*)d_in[10];
    const float* nl_w2   = (const float*)d_in[11];
    const float* c_w     = (const float*)d_in[12];
    const float* c_b     = (const float*)d_in[13];
    const float* c1_w    = (const float*)d_in[14];
    const float* c1_b    = (const float*)d_in[15];

    float *Y, *SA, *SB, *T, *U;
    cudaGetSymbolAddress((void**)&Y,  g_Y);
    cudaGetSymbolAddress((void**)&SA, g_SA);
    cudaGetSymbolAddress((void**)&SB, g_SB);
    cudaGetSymbolAddress((void**)&T,  g_T);
    cudaGetSymbolAddress((void**)&U,  g_U);

    k_xt<<<(NP * BATCH + 127) / 128, 128>>>(flow, Y);
    k_norm<<<1, 320>>>(nodeemb);
    k_lap<<<(NP * NP + 255) / 256, 256>>>();

    // Chebyshev feature recurrence on tensor cores
    dim3 cgrid(BC / 64, NP / 64);
    k_mm<<<cgrid, 128>>>(Y, Y, Y + NPBC, BC, 1.f, 0.f);
    for (int k = 2; k < KORD; k++)
        k_mm<<<cgrid, 128>>>(
            Y + (size_t)(k - 1) * NPBC, Y + (size_t)(k - 2) * NPBC,
            Y + (size_t)k * NPBC, BC, 2.f, -1.f);

    k_combine<<<(NP * BATCH + 127) / 128, 128>>>(cheb_w, cheb_b, cou_w, Y, SA, SB);

    // GL diffusion chain (HMMA path)
    float* p = SA;
    float* c = SB;
    dim3 glgrid(BH / 64, NP / 64);
    for (int it = 0; it < 10; it++) {
        k_gl<<<glgrid, 128>>>(c, p, p, T, U, gl_out, gl_fk, gl_tz_w, gl_tz_b, 0);
        k_gl<<<glgrid, 128>>>(U, c, T, p, T, gl_out, gl_fk, gl_tz_w, gl_tz_b, 1);
        float* tmpp = p; p = c; c = tmpp;
    }
    // after 10 iters: step_0 = p, step_1 = c

    k_nl<<<(NNODE * BATCH) / 128, 128>>>(p, c, lstmW, lstmb, nl_w2,
                                         c_w, c_b, c1_w, c1_b, (float*)d_out);
}